// round 16
// baseline (speedup 1.0000x reference)
#include <cuda_runtime.h>
#include <cstdint>

// ---------------- problem constants ----------------
#define Nn     30000
#define F_IN   128
#define F_H    256
#define NHEAD  8
#define CCH    32
#define NEG_SLOPE 0.2f
#define EMAX   480000
#define SBLK   30          // scan blocks
#define SCHUNK 1000        // elements per scan block

// ---------------- device scratch (no allocs allowed) ----------------
__device__ float g_h  [(size_t)Nn * F_H];
__device__ float g_agg[(size_t)Nn * F_H];
__device__ float g_x2 [(size_t)Nn * F_H];
__device__ float g_as [(size_t)Nn * NHEAD];
__device__ float g_ad [(size_t)Nn * NHEAD];
__device__ float g_den1[(size_t)Nn * NHEAD];
__device__ float g_den2[(size_t)Nn * NHEAD];
__device__ int   g_count [Nn];
__device__ int   g_rowptr[Nn + 1];
__device__ int   g_cursor[Nn];
__device__ int   g_bsum  [SBLK];
__device__ int   g_boff  [SBLK];
__device__ int2  g_cpair [EMAX + 1024];         // (src,dst) per CSR position

__device__ __forceinline__ void red4(float* p, float a, float b, float c, float d) {
    asm volatile("red.global.add.v4.f32 [%0], {%1,%2,%3,%4};"
                 :: "l"(p), "f"(a), "f"(b), "f"(c), "f"(d) : "memory");
}
__device__ __forceinline__ void red1(float* p, float v) {
    asm volatile("red.global.add.f32 [%0], %1;" :: "l"(p), "f"(v) : "memory");
}
__device__ __forceinline__ float leaky(float v) {
    return (v > 0.f) ? v : NEG_SLOPE * v;
}
__device__ __forceinline__ unsigned f2tf32(float f) {
    unsigned u;
    asm("cvt.rna.tf32.f32 %0, %1;" : "=r"(u) : "f"(f));
    return u;
}
__device__ __forceinline__ void mma_tf32(float c[4], unsigned a0, unsigned a1,
                                         unsigned a2, unsigned a3,
                                         unsigned b0, unsigned b1) {
    asm volatile(
        "mma.sync.aligned.m16n8k8.row.col.f32.tf32.tf32.f32 "
        "{%0,%1,%2,%3}, {%4,%5,%6,%7}, {%8,%9}, {%0,%1,%2,%3};"
        : "+f"(c[0]), "+f"(c[1]), "+f"(c[2]), "+f"(c[3])
        : "r"(a0), "r"(a1), "r"(a2), "r"(a3), "r"(b0), "r"(b1));
}

// ---------------- tf32 MMA GEMM: permuted-k smem, float4 fragment loads ----------------
// Smem layout: word(row,k) = row*16 + ((k&3)^swz(row))*4 + (k>>2); one float4
// at group g holds k = {g, g+4, g+8, g+12} -> covers both kk=0 and kk=8 frags.
template <int K>
__global__ void __launch_bounds__(256) k_gemm_tf32(const float* __restrict__ A,
                                                   const float* __restrict__ W,
                                                   float* __restrict__ Cout) {
    __shared__ unsigned As2[128 * 16];   // [row][perm-k], swz = (row>>1)&3
    __shared__ unsigned Bs2[128 * 16];   // [n][perm-k],   swz = (n>>2)&3

    const int tid    = threadIdx.x;
    const int lane   = tid & 31;
    const int warpid = tid >> 5;
    const int row0   = blockIdx.y * 128;
    const int col0   = blockIdx.x * 128;
    const int wm     = (warpid & 3) * 32;
    const int wn     = (warpid >> 2) * 64;
    const int lg     = lane >> 2;
    const int lt     = lane & 3;

    float c[2][8][4];
#pragma unroll
    for (int t = 0; t < 2; t++)
#pragma unroll
        for (int j = 0; j < 8; j++)
#pragma unroll
            for (int r = 0; r < 4; r++) c[t][j][r] = 0.f;

    const int  a_row = tid >> 1;
    const int  a_c0  = (tid & 1) * 8;
    const int  b_k   = tid >> 4;
    const int  b_n0  = (tid & 15) * 4;
    const bool a_ok  = (row0 + a_row) < Nn;

    float4 a_reg[2], b_reg[2];
#pragma unroll
    for (int i = 0; i < 2; i++) {
        a_reg[i] = make_float4(0.f, 0.f, 0.f, 0.f);
        if (a_ok)
            a_reg[i] = *(const float4*)(A + (size_t)(row0 + a_row) * K + a_c0 + i * 4);
        b_reg[i] = *(const float4*)(W + (size_t)b_k * F_H + col0 + b_n0 + i * 64);
    }

    const unsigned aswz = (a_row >> 1) & 3;
    const unsigned bkg  = b_k & 3, bkp = b_k >> 2;

    for (int k0 = 0; k0 < K; k0 += 16) {
        // ---- stage with permuted-k scatter ----
#pragma unroll
        for (int i = 0; i < 2; i++) {
            float4 v = a_reg[i];
            int cbase = a_c0 + i * 4;
            float vv[4] = {v.x, v.y, v.z, v.w};
#pragma unroll
            for (int e = 0; e < 4; e++) {
                int k = cbase + e;
                As2[a_row * 16 + (((k & 3) ^ aswz) << 2) + (k >> 2)] = f2tf32(vv[e]);
            }
            v = b_reg[i];
            float ww[4] = {v.x, v.y, v.z, v.w};
#pragma unroll
            for (int e = 0; e < 4; e++) {
                int n = b_n0 + i * 64 + e;
                Bs2[n * 16 + (((bkg ^ ((n >> 2) & 3))) << 2) + bkp] = f2tf32(ww[e]);
            }
        }
        __syncthreads();

        // ---- prefetch next tile ----
        if (k0 + 16 < K) {
#pragma unroll
            for (int i = 0; i < 2; i++) {
                a_reg[i] = make_float4(0.f, 0.f, 0.f, 0.f);
                if (a_ok)
                    a_reg[i] = *(const float4*)(A + (size_t)(row0 + a_row) * K + k0 + 16 + a_c0 + i * 4);
                b_reg[i] = *(const float4*)(W + (size_t)(k0 + 16 + b_k) * F_H + col0 + b_n0 + i * 64);
            }
        }

        // ---- A fragments: 4 x LDS.128 covers both kk=0 and kk=8 ----
        uint4 fa[2][2];
#pragma unroll
        for (int t = 0; t < 2; t++) {
            int r0 = wm + t * 16 + lg;
            int r1 = r0 + 8;
            fa[t][0] = *(const uint4*)&As2[r0 * 16 + ((lt ^ ((r0 >> 1) & 3)) << 2)];
            fa[t][1] = *(const uint4*)&As2[r1 * 16 + ((lt ^ ((r1 >> 1) & 3)) << 2)];
        }

        // ---- B fragment per j: 1 x LDS.128 feeds 4 MMAs ----
#pragma unroll
        for (int j = 0; j < 8; j++) {
            int n = wn + j * 8 + lg;
            uint4 fb = *(const uint4*)&Bs2[n * 16 + ((lt ^ ((n >> 2) & 3)) << 2)];
#pragma unroll
            for (int t = 0; t < 2; t++) {
                mma_tf32(c[t][j], fa[t][0].x, fa[t][1].x, fa[t][0].y, fa[t][1].y,
                         fb.x, fb.y);                       // kk = 0
                mma_tf32(c[t][j], fa[t][0].z, fa[t][1].z, fa[t][0].w, fa[t][1].w,
                         fb.z, fb.w);                       // kk = 8
            }
        }
        __syncthreads();
    }

#pragma unroll
    for (int t = 0; t < 2; t++) {
        int r0 = row0 + wm + t * 16 + lg;
#pragma unroll
        for (int j = 0; j < 8; j++) {
            int cc = col0 + wn + j * 8 + lt * 2;
            if (r0 < Nn)
                *(float2*)(Cout + (size_t)r0 * F_H + cc) = make_float2(c[t][j][0], c[t][j][1]);
            if (r0 + 8 < Nn)
                *(float2*)(Cout + (size_t)(r0 + 8) * F_H + cc) = make_float2(c[t][j][2], c[t][j][3]);
        }
    }
}

// ---------------- alpha projections ----------------
__global__ void k_alpha(const float* __restrict__ a_src, const float* __restrict__ a_dst) {
    int idx = blockIdx.x * blockDim.x + threadIdx.x;
    if (idx >= Nn * NHEAD) return;
    int n = idx >> 3, h = idx & 7;
    const float4* hp = (const float4*)(g_h + (size_t)n * F_H + h * CCH);
    const float4* as = (const float4*)(a_src + h * CCH);
    const float4* ad = (const float4*)(a_dst + h * CCH);
    float s = 0.f, d = 0.f;
#pragma unroll
    for (int i = 0; i < 8; i++) {
        float4 v = hp[i], a = as[i], b = ad[i];
        s += v.x * a.x + v.y * a.y + v.z * a.z + v.w * a.w;
        d += v.x * b.x + v.y * b.y + v.z * b.z + v.w * b.w;
    }
    g_as[idx] = s;
    g_ad[idx] = d;
}

// ---------------- init ----------------
__global__ void k_zero_agg() {
    int i = blockIdx.x * blockDim.x + threadIdx.x;
    if (i < Nn * F_H) g_agg[i] = 0.f;
    if (i < Nn * NHEAD) { g_den1[i] = 0.f; g_den2[i] = 0.f; }
}
__global__ void k_zero_count() {
    int i = blockIdx.x * blockDim.x + threadIdx.x;
    if (i < Nn) g_count[i] = 0;
}
__global__ void k_count(const int* __restrict__ ei, int E) {
    int e = blockIdx.x * blockDim.x + threadIdx.x;
    if (e < E) atomicAdd(&g_count[ei[E + e]], 1);
}
__global__ void __launch_bounds__(1024) k_scan1() {
    __shared__ int red[32];
    int b = blockIdx.x, t = threadIdx.x;
    int v = (t < SCHUNK) ? g_count[b * SCHUNK + t] : 0;
#pragma unroll
    for (int o = 16; o > 0; o >>= 1) v += __shfl_down_sync(0xFFFFFFFFu, v, o);
    if ((t & 31) == 0) red[t >> 5] = v;
    __syncthreads();
    if (t < 32) {
        int s = red[t];
#pragma unroll
        for (int o = 16; o > 0; o >>= 1) s += __shfl_down_sync(0xFFFFFFFFu, s, o);
        if (t == 0) g_bsum[b] = s;
    }
}
__global__ void k_scan2() {
    int t = threadIdx.x;
    int v = (t < SBLK) ? g_bsum[t] : 0;
    int incl = v;
#pragma unroll
    for (int o = 1; o < 32; o <<= 1) {
        int u = __shfl_up_sync(0xFFFFFFFFu, incl, o);
        if (t >= o) incl += u;
    }
    if (t < SBLK) g_boff[t] = incl - v;
}
__global__ void __launch_bounds__(1024) k_scan3(int E) {
    __shared__ int sv[1024];
    int b = blockIdx.x, t = threadIdx.x;
    int c = (t < SCHUNK) ? g_count[b * SCHUNK + t] : 0;
    sv[t] = c;
    __syncthreads();
    for (int o = 1; o < 1024; o <<= 1) {
        int u = (t >= o) ? sv[t - o] : 0;
        __syncthreads();
        sv[t] += u;
        __syncthreads();
    }
    if (t < SCHUNK) {
        int excl = sv[t] - c + g_boff[b];
        g_rowptr[b * SCHUNK + t] = excl;
        g_cursor[b * SCHUNK + t] = excl;
    }
    if (b == SBLK - 1 && t == 0) g_rowptr[Nn] = E;
}
__global__ void k_scatter2(const int* __restrict__ ei, int E) {
    int e = blockIdx.x * blockDim.x + threadIdx.x;
    if (e >= E) return;
    int src = ei[e];
    int dst = ei[E + e];
    int pos = atomicAdd(&g_cursor[dst], 1);
    g_cpair[pos] = make_int2(src, dst);
}

// ---------------- fused CSR dedup push: weights + den + aggregate in one pass --------
__global__ void __launch_bounds__(256) k_edge_csr(int E, float* __restrict__ den) {
    int tid = blockIdx.x * blockDim.x + threadIdx.x;
    int g = tid >> 3, j = tid & 7;
    int base = g * 8;
    unsigned mask = __ballot_sync(0xFFFFFFFFu, base < E);
    if (base >= E) return;
    int cnt = min(8, E - base);

    int s[8], d[8];
    if (cnt == 8) {
        const int4* pp = (const int4*)&g_cpair[base];
#pragma unroll
        for (int q = 0; q < 4; q++) {
            int4 pr = pp[q];
            s[q * 2] = pr.x;     d[q * 2] = pr.y;
            s[q * 2 + 1] = pr.z; d[q * 2 + 1] = pr.w;
        }
    } else {
#pragma unroll
        for (int p = 0; p < 8; p++) {
            int q = (p < cnt) ? base + p : base + cnt - 1;
            int2 pr = g_cpair[q];
            s[p] = pr.x;
            d[p] = pr.y;
        }
    }

    float av[8], dv[8], wl[8];
#pragma unroll
    for (int p = 0; p < 8; p++) av[p] = __ldg(&g_as[s[p] * NHEAD + j]);
#pragma unroll
    for (int p = 0; p < 8; p++) dv[p] = __ldg(&g_ad[d[p] * NHEAD + j]);
#pragma unroll
    for (int p = 0; p < 8; p++) {
        float w = __expf(leaky(av[p] + dv[p]));
        wl[p] = (p < cnt) ? w : 0.f;
    }

    float4 acc[8];
    float  dj;
    int cur = d[0];
    {
        float wh[8];
#pragma unroll
        for (int i = 0; i < 8; i++) wh[i] = __shfl_sync(mask, wl[0], i, 8);
        const float4* hp = (const float4*)(g_h + (size_t)s[0] * F_H) + j;
#pragma unroll
        for (int i = 0; i < 8; i++) {
            float4 hv = __ldg(hp + i * 8);
            acc[i] = make_float4(wh[i] * hv.x, wh[i] * hv.y, wh[i] * hv.z, wh[i] * hv.w);
        }
        dj = wl[0];
    }
#pragma unroll
    for (int p = 1; p < 8; p++) {
        float wh[8];
#pragma unroll
        for (int i = 0; i < 8; i++) wh[i] = __shfl_sync(mask, wl[p], i, 8);
        const float4* hp = (const float4*)(g_h + (size_t)s[p] * F_H) + j;
        if (d[p] != cur) {
            float* op = g_agg + (size_t)cur * F_H + j * 4;
#pragma unroll
            for (int i = 0; i < 8; i++)
                red4(op + i * 32, acc[i].x, acc[i].y, acc[i].z, acc[i].w);
            red1(&den[cur * NHEAD + j], dj);
            cur = d[p];
            dj = wl[p];
#pragma unroll
            for (int i = 0; i < 8; i++) {
                float4 hv = __ldg(hp + i * 8);
                acc[i] = make_float4(wh[i] * hv.x, wh[i] * hv.y, wh[i] * hv.z, wh[i] * hv.w);
            }
        } else {
            dj += wl[p];
#pragma unroll
            for (int i = 0; i < 8; i++) {
                float4 hv = __ldg(hp + i * 8);
                acc[i].x += wh[i] * hv.x; acc[i].y += wh[i] * hv.y;
                acc[i].z += wh[i] * hv.z; acc[i].w += wh[i] * hv.w;
            }
        }
    }
    float* op = g_agg + (size_t)cur * F_H + j * 4;
#pragma unroll
    for (int i = 0; i < 8; i++)
        red4(op + i * 32, acc[i].x, acc[i].y, acc[i].z, acc[i].w);
    red1(&den[cur * NHEAD + j], dj);
}

// ---------------- epilogue layer 1 ----------------
__global__ void k_elu1(const float* __restrict__ b) {
    int idx = blockIdx.x * blockDim.x + threadIdx.x;
    if (idx >= Nn * F_H) return;
    int n = idx >> 8, f = idx & 255, h = f >> 5;
    float ws = __expf(leaky(g_as[n * NHEAD + h] + g_ad[n * NHEAD + h]));
    float num = g_agg[idx] + ws * g_h[idx];
    float den = g_den1[n * NHEAD + h] + ws;
    float v = num / den + b[f];
    g_x2[idx] = (v > 0.f) ? v : expm1f(v);
    g_agg[idx] = 0.f;
}

// ---------------- epilogue layer 2 + linear head ----------------
__global__ void k_final(const float* __restrict__ b2, const float* __restrict__ Wl,
                        const float* __restrict__ bl, float* __restrict__ out) {
    int gid = blockIdx.x * blockDim.x + threadIdx.x;
    int n = gid >> 5, lane = gid & 31;
    if (n >= Nn) return;
    float s = 0.f;
#pragma unroll
    for (int k = 0; k < 8; k++) {
        int f = lane + 32 * k;
        float ws = __expf(leaky(g_as[n * NHEAD + k] + g_ad[n * NHEAD + k]));
        float num = g_agg[(size_t)n * F_H + f] + ws * g_h[(size_t)n * F_H + f];
        float den = g_den2[n * NHEAD + k] + ws;
        float v = num / den + b2[f];
        v = (v > 0.f) ? v : expm1f(v);
        s += v * Wl[f];
    }
#pragma unroll
    for (int o = 16; o > 0; o >>= 1) s += __shfl_down_sync(0xFFFFFFFFu, s, o);
    if (lane == 0) out[n] = s + bl[0];
}

// ---------------- host ----------------
extern "C" void kernel_launch(void* const* d_in, const int* in_sizes, int n_in,
                              void* d_out, int out_size) {
    const float* x   = (const float*)d_in[0];
    const int*   ei  = (const int*)  d_in[1];
    const float* W1  = (const float*)d_in[2];
    const float* a1s = (const float*)d_in[3];
    const float* a1d = (const float*)d_in[4];
    const float* b1  = (const float*)d_in[5];
    const float* W2  = (const float*)d_in[6];
    const float* a2s = (const float*)d_in[7];
    const float* a2d = (const float*)d_in[8];
    const float* b2  = (const float*)d_in[9];
    const float* Wl  = (const float*)d_in[10];
    const float* bl  = (const float*)d_in[11];
    float* out = (float*)d_out;

    const int E = in_sizes[1] / 2;          // 480000

    float* g_h_p;    cudaGetSymbolAddress((void**)&g_h_p,    g_h);
    float* g_x2_p;   cudaGetSymbolAddress((void**)&g_x2_p,   g_x2);
    float* g_den1_p; cudaGetSymbolAddress((void**)&g_den1_p, g_den1);
    float* g_den2_p; cudaGetSymbolAddress((void**)&g_den2_p, g_den2);

    const int T = 256;
    dim3 gemm_grid(F_H / 128, (Nn + 127) / 128);
    int nh_blocks = (Nn * NHEAD + T - 1) / T;
    int e_blocks  = (E + T - 1) / T;
    int nf_blocks = (Nn * F_H + T - 1) / T;
    int fin_blocks = (Nn * 32 + T - 1) / T;

    // ---------- prep; layer-1 GEMM at launch index 3 (profiled slot) ----------
    k_zero_agg<<<nf_blocks, T>>>();                       // 0
    k_zero_count<<<(Nn + T - 1) / T, T>>>();              // 1
    k_count<<<e_blocks, T>>>(ei, E);                      // 2
    k_gemm_tf32<F_IN><<<gemm_grid, T>>>(x, W1, g_h_p);    // 3  <- profiled
    k_scan1<<<SBLK, 1024>>>();                            // 4
    k_scan2<<<1, 32>>>();                                 // 5
    k_scan3<<<SBLK, 1024>>>(E);                           // 6
    k_scatter2<<<e_blocks, T>>>(ei, E);                   // 7

    // ---------- layer 1 ----------
    k_alpha<<<nh_blocks, T>>>(a1s, a1d);
    k_edge_csr<<<e_blocks, T>>>(E, g_den1_p);
    k_elu1<<<nf_blocks, T>>>(b1);

    // ---------- layer 2 ----------
    k_gemm_tf32<F_H><<<gemm_grid, T>>>(g_x2_p, W2, g_h_p);
    k_alpha<<<nh_blocks, T>>>(a2s, a2d);
    k_edge_csr<<<e_blocks, T>>>(E, g_den2_p);
    k_final<<<fin_blocks, T>>>(b2, Wl, bl, out);
}

// round 17
// speedup vs baseline: 1.0635x; 1.0635x over previous
#include <cuda_runtime.h>
#include <cstdint>

// ---------------- problem constants ----------------
#define Nn     30000
#define F_IN   128
#define F_H    256
#define NHEAD  8
#define CCH    32
#define NEG_SLOPE 0.2f
#define EMAX   480000
#define SBLK   30          // scan blocks
#define SCHUNK 1000        // elements per scan block

// ---------------- device scratch (no allocs allowed) ----------------
__device__ float g_h  [(size_t)Nn * F_H];
__device__ float g_agg[(size_t)Nn * F_H];
__device__ float g_x2 [(size_t)Nn * F_H];
__device__ float g_as [(size_t)Nn * NHEAD];
__device__ float g_ad [(size_t)Nn * NHEAD];
__device__ float g_den1[(size_t)Nn * NHEAD];
__device__ float g_den2[(size_t)Nn * NHEAD];
__device__ int   g_count [Nn];
__device__ int   g_rowptr[Nn + 1];
__device__ int   g_cursor[Nn];
__device__ int   g_bsum  [SBLK];
__device__ int   g_boff  [SBLK];
__device__ int2  g_cpair [EMAX + 1024];         // (src,dst) per CSR position

__device__ __forceinline__ void red4(float* p, float a, float b, float c, float d) {
    asm volatile("red.global.add.v4.f32 [%0], {%1,%2,%3,%4};"
                 :: "l"(p), "f"(a), "f"(b), "f"(c), "f"(d) : "memory");
}
__device__ __forceinline__ void red1(float* p, float v) {
    asm volatile("red.global.add.f32 [%0], %1;" :: "l"(p), "f"(v) : "memory");
}
__device__ __forceinline__ float leaky(float v) {
    return (v > 0.f) ? v : NEG_SLOPE * v;
}
__device__ __forceinline__ unsigned f2tf32(float f) {
    unsigned u;
    asm("cvt.rna.tf32.f32 %0, %1;" : "=r"(u) : "f"(f));
    return u;
}
__device__ __forceinline__ void mma_tf32(float c[4], const unsigned a[4], const unsigned b[2]) {
    asm volatile(
        "mma.sync.aligned.m16n8k8.row.col.f32.tf32.tf32.f32 "
        "{%0,%1,%2,%3}, {%4,%5,%6,%7}, {%8,%9}, {%0,%1,%2,%3};"
        : "+f"(c[0]), "+f"(c[1]), "+f"(c[2]), "+f"(c[3])
        : "r"(a[0]), "r"(a[1]), "r"(a[2]), "r"(a[3]), "r"(b[0]), "r"(b[1]));
}

// ---------------- tf32 MMA GEMM: round-14 layout + double-buffered smem ----------------
#define AP 20
#define BP 136

template <int K>
__global__ void __launch_bounds__(256) k_gemm_tf32(const float* __restrict__ A,
                                                   const float* __restrict__ W,
                                                   float* __restrict__ Cout) {
    __shared__ unsigned As[2][128 * AP];
    __shared__ unsigned Bs[2][16 * BP];

    const int tid    = threadIdx.x;
    const int lane   = tid & 31;
    const int warpid = tid >> 5;
    const int row0   = blockIdx.y * 128;
    const int col0   = blockIdx.x * 128;
    const int wm     = (warpid & 3) * 32;
    const int wn     = (warpid >> 2) * 64;
    const int lg     = lane >> 2;
    const int lt     = lane & 3;

    float c[2][8][4];
#pragma unroll
    for (int t = 0; t < 2; t++)
#pragma unroll
        for (int j = 0; j < 8; j++)
#pragma unroll
            for (int r = 0; r < 4; r++) c[t][j][r] = 0.f;

    const int  a_row = tid >> 1;
    const int  a_c0  = (tid & 1) * 8;
    const int  b_k   = tid >> 4;
    const int  b_n0  = (tid & 15) * 4;
    const bool a_ok  = (row0 + a_row) < Nn;

    float4 a_reg[2], b_reg[2];
    // prologue: tile 0 -> regs -> buf 0
#pragma unroll
    for (int i = 0; i < 2; i++) {
        a_reg[i] = make_float4(0.f, 0.f, 0.f, 0.f);
        if (a_ok)
            a_reg[i] = *(const float4*)(A + (size_t)(row0 + a_row) * K + a_c0 + i * 4);
        b_reg[i] = *(const float4*)(W + (size_t)b_k * F_H + col0 + b_n0 + i * 64);
    }
#pragma unroll
    for (int i = 0; i < 2; i++) {
        float4 v = a_reg[i];
        *(uint4*)&As[0][a_row * AP + a_c0 + i * 4] =
            make_uint4(f2tf32(v.x), f2tf32(v.y), f2tf32(v.z), f2tf32(v.w));
        v = b_reg[i];
        *(uint4*)&Bs[0][b_k * BP + b_n0 + i * 64] =
            make_uint4(f2tf32(v.x), f2tf32(v.y), f2tf32(v.z), f2tf32(v.w));
    }
    __syncthreads();

    const int NT = K / 16;
    for (int t0 = 0; t0 < NT; t0++) {
        const int cur = t0 & 1;
        // prefetch tile t0+1 into registers (latency hidden behind MMAs)
        if (t0 + 1 < NT) {
            int k0 = (t0 + 1) * 16;
#pragma unroll
            for (int i = 0; i < 2; i++) {
                a_reg[i] = make_float4(0.f, 0.f, 0.f, 0.f);
                if (a_ok)
                    a_reg[i] = *(const float4*)(A + (size_t)(row0 + a_row) * K + k0 + a_c0 + i * 4);
                b_reg[i] = *(const float4*)(W + (size_t)(k0 + b_k) * F_H + col0 + b_n0 + i * 64);
            }
        }

        // compute from buf[cur]
#pragma unroll
        for (int kk = 0; kk < 16; kk += 8) {
            unsigned a[2][4];
#pragma unroll
            for (int t = 0; t < 2; t++) {
                int mr = wm + t * 16;
                a[t][0] = As[cur][(mr + lg) * AP + kk + lt];
                a[t][1] = As[cur][(mr + lg + 8) * AP + kk + lt];
                a[t][2] = As[cur][(mr + lg) * AP + kk + lt + 4];
                a[t][3] = As[cur][(mr + lg + 8) * AP + kk + lt + 4];
            }
#pragma unroll
            for (int j = 0; j < 8; j++) {
                unsigned b[2];
                int n = wn + j * 8 + lg;
                b[0] = Bs[cur][(kk + lt) * BP + n];
                b[1] = Bs[cur][(kk + lt + 4) * BP + n];
                mma_tf32(c[0][j], a[0], b);
                mma_tf32(c[1][j], a[1], b);
            }
        }

        // store prefetched tile into the other buffer (overlaps with peers' MMAs)
        if (t0 + 1 < NT) {
#pragma unroll
            for (int i = 0; i < 2; i++) {
                float4 v = a_reg[i];
                *(uint4*)&As[cur ^ 1][a_row * AP + a_c0 + i * 4] =
                    make_uint4(f2tf32(v.x), f2tf32(v.y), f2tf32(v.z), f2tf32(v.w));
                v = b_reg[i];
                *(uint4*)&Bs[cur ^ 1][b_k * BP + b_n0 + i * 64] =
                    make_uint4(f2tf32(v.x), f2tf32(v.y), f2tf32(v.z), f2tf32(v.w));
            }
        }
        __syncthreads();
    }

#pragma unroll
    for (int t = 0; t < 2; t++) {
        int r0 = row0 + wm + t * 16 + lg;
#pragma unroll
        for (int j = 0; j < 8; j++) {
            int cc = col0 + wn + j * 8 + lt * 2;
            if (r0 < Nn)
                *(float2*)(Cout + (size_t)r0 * F_H + cc) = make_float2(c[t][j][0], c[t][j][1]);
            if (r0 + 8 < Nn)
                *(float2*)(Cout + (size_t)(r0 + 8) * F_H + cc) = make_float2(c[t][j][2], c[t][j][3]);
        }
    }
}

// ---------------- alpha projections ----------------
__global__ void k_alpha(const float* __restrict__ a_src, const float* __restrict__ a_dst) {
    int idx = blockIdx.x * blockDim.x + threadIdx.x;
    if (idx >= Nn * NHEAD) return;
    int n = idx >> 3, h = idx & 7;
    const float4* hp = (const float4*)(g_h + (size_t)n * F_H + h * CCH);
    const float4* as = (const float4*)(a_src + h * CCH);
    const float4* ad = (const float4*)(a_dst + h * CCH);
    float s = 0.f, d = 0.f;
#pragma unroll
    for (int i = 0; i < 8; i++) {
        float4 v = hp[i], a = as[i], b = ad[i];
        s += v.x * a.x + v.y * a.y + v.z * a.z + v.w * a.w;
        d += v.x * b.x + v.y * b.y + v.z * b.z + v.w * b.w;
    }
    g_as[idx] = s;
    g_ad[idx] = d;
}

// ---------------- init ----------------
__global__ void k_zero_agg() {
    int i = blockIdx.x * blockDim.x + threadIdx.x;
    if (i < Nn * F_H) g_agg[i] = 0.f;
    if (i < Nn * NHEAD) { g_den1[i] = 0.f; g_den2[i] = 0.f; }
}
__global__ void k_zero_count() {
    int i = blockIdx.x * blockDim.x + threadIdx.x;
    if (i < Nn) g_count[i] = 0;
}
__global__ void k_count(const int* __restrict__ ei, int E) {
    int e = blockIdx.x * blockDim.x + threadIdx.x;
    if (e < E) atomicAdd(&g_count[ei[E + e]], 1);
}
__global__ void __launch_bounds__(1024) k_scan1() {
    __shared__ int red[32];
    int b = blockIdx.x, t = threadIdx.x;
    int v = (t < SCHUNK) ? g_count[b * SCHUNK + t] : 0;
#pragma unroll
    for (int o = 16; o > 0; o >>= 1) v += __shfl_down_sync(0xFFFFFFFFu, v, o);
    if ((t & 31) == 0) red[t >> 5] = v;
    __syncthreads();
    if (t < 32) {
        int s = red[t];
#pragma unroll
        for (int o = 16; o > 0; o >>= 1) s += __shfl_down_sync(0xFFFFFFFFu, s, o);
        if (t == 0) g_bsum[b] = s;
    }
}
__global__ void k_scan2() {
    int t = threadIdx.x;
    int v = (t < SBLK) ? g_bsum[t] : 0;
    int incl = v;
#pragma unroll
    for (int o = 1; o < 32; o <<= 1) {
        int u = __shfl_up_sync(0xFFFFFFFFu, incl, o);
        if (t >= o) incl += u;
    }
    if (t < SBLK) g_boff[t] = incl - v;
}
__global__ void __launch_bounds__(1024) k_scan3(int E) {
    __shared__ int sv[1024];
    int b = blockIdx.x, t = threadIdx.x;
    int c = (t < SCHUNK) ? g_count[b * SCHUNK + t] : 0;
    sv[t] = c;
    __syncthreads();
    for (int o = 1; o < 1024; o <<= 1) {
        int u = (t >= o) ? sv[t - o] : 0;
        __syncthreads();
        sv[t] += u;
        __syncthreads();
    }
    if (t < SCHUNK) {
        int excl = sv[t] - c + g_boff[b];
        g_rowptr[b * SCHUNK + t] = excl;
        g_cursor[b * SCHUNK + t] = excl;
    }
    if (b == SBLK - 1 && t == 0) g_rowptr[Nn] = E;
}
__global__ void k_scatter2(const int* __restrict__ ei, int E) {
    int e = blockIdx.x * blockDim.x + threadIdx.x;
    if (e >= E) return;
    int src = ei[e];
    int dst = ei[E + e];
    int pos = atomicAdd(&g_cursor[dst], 1);
    g_cpair[pos] = make_int2(src, dst);
}

// ---------------- fused CSR dedup push: weights + den + aggregate in one pass --------
__global__ void __launch_bounds__(256) k_edge_csr(int E, float* __restrict__ den) {
    int tid = blockIdx.x * blockDim.x + threadIdx.x;
    int g = tid >> 3, j = tid & 7;
    int base = g * 8;
    unsigned mask = __ballot_sync(0xFFFFFFFFu, base < E);
    if (base >= E) return;
    int cnt = min(8, E - base);

    int s[8], d[8];
    if (cnt == 8) {
        const int4* pp = (const int4*)&g_cpair[base];
#pragma unroll
        for (int q = 0; q < 4; q++) {
            int4 pr = pp[q];
            s[q * 2] = pr.x;     d[q * 2] = pr.y;
            s[q * 2 + 1] = pr.z; d[q * 2 + 1] = pr.w;
        }
    } else {
#pragma unroll
        for (int p = 0; p < 8; p++) {
            int q = (p < cnt) ? base + p : base + cnt - 1;
            int2 pr = g_cpair[q];
            s[p] = pr.x;
            d[p] = pr.y;
        }
    }

    float av[8], dv[8], wl[8];
#pragma unroll
    for (int p = 0; p < 8; p++) av[p] = __ldg(&g_as[s[p] * NHEAD + j]);
#pragma unroll
    for (int p = 0; p < 8; p++) dv[p] = __ldg(&g_ad[d[p] * NHEAD + j]);
#pragma unroll
    for (int p = 0; p < 8; p++) {
        float w = __expf(leaky(av[p] + dv[p]));
        wl[p] = (p < cnt) ? w : 0.f;
    }

    float4 acc[8];
    float  dj;
    int cur = d[0];
    {
        float wh[8];
#pragma unroll
        for (int i = 0; i < 8; i++) wh[i] = __shfl_sync(mask, wl[0], i, 8);
        const float4* hp = (const float4*)(g_h + (size_t)s[0] * F_H) + j;
#pragma unroll
        for (int i = 0; i < 8; i++) {
            float4 hv = __ldg(hp + i * 8);
            acc[i] = make_float4(wh[i] * hv.x, wh[i] * hv.y, wh[i] * hv.z, wh[i] * hv.w);
        }
        dj = wl[0];
    }
#pragma unroll
    for (int p = 1; p < 8; p++) {
        float wh[8];
#pragma unroll
        for (int i = 0; i < 8; i++) wh[i] = __shfl_sync(mask, wl[p], i, 8);
        const float4* hp = (const float4*)(g_h + (size_t)s[p] * F_H) + j;
        if (d[p] != cur) {
            float* op = g_agg + (size_t)cur * F_H + j * 4;
#pragma unroll
            for (int i = 0; i < 8; i++)
                red4(op + i * 32, acc[i].x, acc[i].y, acc[i].z, acc[i].w);
            red1(&den[cur * NHEAD + j], dj);
            cur = d[p];
            dj = wl[p];
#pragma unroll
            for (int i = 0; i < 8; i++) {
                float4 hv = __ldg(hp + i * 8);
                acc[i] = make_float4(wh[i] * hv.x, wh[i] * hv.y, wh[i] * hv.z, wh[i] * hv.w);
            }
        } else {
            dj += wl[p];
#pragma unroll
            for (int i = 0; i < 8; i++) {
                float4 hv = __ldg(hp + i * 8);
                acc[i].x += wh[i] * hv.x; acc[i].y += wh[i] * hv.y;
                acc[i].z += wh[i] * hv.z; acc[i].w += wh[i] * hv.w;
            }
        }
    }
    float* op = g_agg + (size_t)cur * F_H + j * 4;
#pragma unroll
    for (int i = 0; i < 8; i++)
        red4(op + i * 32, acc[i].x, acc[i].y, acc[i].z, acc[i].w);
    red1(&den[cur * NHEAD + j], dj);
}

// ---------------- epilogue layer 1 ----------------
__global__ void k_elu1(const float* __restrict__ b) {
    int idx = blockIdx.x * blockDim.x + threadIdx.x;
    if (idx >= Nn * F_H) return;
    int n = idx >> 8, f = idx & 255, h = f >> 5;
    float ws = __expf(leaky(g_as[n * NHEAD + h] + g_ad[n * NHEAD + h]));
    float num = g_agg[idx] + ws * g_h[idx];
    float den = g_den1[n * NHEAD + h] + ws;
    float v = num / den + b[f];
    g_x2[idx] = (v > 0.f) ? v : expm1f(v);
    g_agg[idx] = 0.f;
}

// ---------------- epilogue layer 2 + linear head ----------------
__global__ void k_final(const float* __restrict__ b2, const float* __restrict__ Wl,
                        const float* __restrict__ bl, float* __restrict__ out) {
    int gid = blockIdx.x * blockDim.x + threadIdx.x;
    int n = gid >> 5, lane = gid & 31;
    if (n >= Nn) return;
    float s = 0.f;
#pragma unroll
    for (int k = 0; k < 8; k++) {
        int f = lane + 32 * k;
        float ws = __expf(leaky(g_as[n * NHEAD + k] + g_ad[n * NHEAD + k]));
        float num = g_agg[(size_t)n * F_H + f] + ws * g_h[(size_t)n * F_H + f];
        float den = g_den2[n * NHEAD + k] + ws;
        float v = num / den + b2[f];
        v = (v > 0.f) ? v : expm1f(v);
        s += v * Wl[f];
    }
#pragma unroll
    for (int o = 16; o > 0; o >>= 1) s += __shfl_down_sync(0xFFFFFFFFu, s, o);
    if (lane == 0) out[n] = s + bl[0];
}

// ---------------- host ----------------
extern "C" void kernel_launch(void* const* d_in, const int* in_sizes, int n_in,
                              void* d_out, int out_size) {
    const float* x   = (const float*)d_in[0];
    const int*   ei  = (const int*)  d_in[1];
    const float* W1  = (const float*)d_in[2];
    const float* a1s = (const float*)d_in[3];
    const float* a1d = (const float*)d_in[4];
    const float* b1  = (const float*)d_in[5];
    const float* W2  = (const float*)d_in[6];
    const float* a2s = (const float*)d_in[7];
    const float* a2d = (const float*)d_in[8];
    const float* b2  = (const float*)d_in[9];
    const float* Wl  = (const float*)d_in[10];
    const float* bl  = (const float*)d_in[11];
    float* out = (float*)d_out;

    const int E = in_sizes[1] / 2;          // 480000

    float* g_h_p;    cudaGetSymbolAddress((void**)&g_h_p,    g_h);
    float* g_x2_p;   cudaGetSymbolAddress((void**)&g_x2_p,   g_x2);
    float* g_den1_p; cudaGetSymbolAddress((void**)&g_den1_p, g_den1);
    float* g_den2_p; cudaGetSymbolAddress((void**)&g_den2_p, g_den2);

    const int T = 256;
    dim3 gemm_grid(F_H / 128, (Nn + 127) / 128);
    int nh_blocks = (Nn * NHEAD + T - 1) / T;
    int e_blocks  = (E + T - 1) / T;
    int nf_blocks = (Nn * F_H + T - 1) / T;
    int fin_blocks = (Nn * 32 + T - 1) / T;

    // ---------- prep; layer-1 GEMM at launch index 3 (profiled slot) ----------
    k_zero_agg<<<nf_blocks, T>>>();                       // 0
    k_zero_count<<<(Nn + T - 1) / T, T>>>();              // 1
    k_count<<<e_blocks, T>>>(ei, E);                      // 2
    k_gemm_tf32<F_IN><<<gemm_grid, T>>>(x, W1, g_h_p);    // 3  <- profiled
    k_scan1<<<SBLK, 1024>>>();                            // 4
    k_scan2<<<1, 32>>>();                                 // 5
    k_scan3<<<SBLK, 1024>>>(E);                           // 6
    k_scatter2<<<e_blocks, T>>>(ei, E);                   // 7

    // ---------- layer 1 ----------
    k_alpha<<<nh_blocks, T>>>(a1s, a1d);
    k_edge_csr<<<e_blocks, T>>>(E, g_den1_p);
    k_elu1<<<nf_blocks, T>>>(b1);

    // ---------- layer 2 ----------
    k_gemm_tf32<F_H><<<gemm_grid, T>>>(g_x2_p, W2, g_h_p);
    k_alpha<<<nh_blocks, T>>>(a2s, a2d);
    k_edge_csr<<<e_blocks, T>>>(E, g_den2_p);
    k_final<<<fin_blocks, T>>>(b2, Wl, bl, out);
}